// round 14
// baseline (speedup 1.0000x reference)
#include <cuda_runtime.h>
#include <cuda_fp16.h>
#include <math.h>
#include <stdint.h>

#define LQ 8192
#define HD 1024
#define PD 1024
#define N1 2048
#define NCHUNK 128
#define CHUNK 64

// ---- GEMM tile config (fp16 m16n8k16) ----
#define BM 128
#define BN 256
#define BK 64
#define NST 3
#define ASTRH 72
#define ASTGH (128 * ASTRH)
#define STGH (384 * ASTRH)
#define SMEM_BYTES (NST * STGH * 2)       // 165888
#define BSCALE 1024.0f
#define BSCALE_INV (1.0f / 1024.0f)

// ---------------- device scratch ----------------
// complex-interleaved layouts: Bu/xs columns [re0 im0 ...]; Bbar rows 2p/2p+1; Cf cols 2p/2p+1
__device__ __half g_Bbar[N1 * HD];        // row 2p = re_p, row 2p+1 = im_p (scaled by 1024)
__device__ __half g_Cf[HD * N1];          // col 2p = C_re, col 2p+1 = -C_im
__device__ __half g_xsh[LQ * N1];         // scan output fp16, interleaved
__device__ __half g_Buh[LQ * N1];         // fp16 scan input (scaled), interleaved
__device__ float g_Abar_re[PD], g_Abar_im[PD];
__device__ float g_coef_re[PD], g_coef_im[PD];
__device__ float g_AS_re[PD],   g_AS_im[PD];
__device__ float g_E_re[NCHUNK * PD], g_E_im[NCHUNK * PD];
__device__ float g_pref_re[NCHUNK * PD], g_pref_im[NCHUNK * PD];

// ---------------- helpers ----------------
__device__ __forceinline__ uint32_t smem_u32(const void* p) {
    uint32_t a;
    asm("{ .reg .u64 t; cvta.to.shared.u64 t, %1; cvt.u32.u64 %0, t; }" : "=r"(a) : "l"(p));
    return a;
}
__device__ __forceinline__ void cp16(uint32_t saddr, const void* gptr) {
    asm volatile("cp.async.ca.shared.global [%0], [%1], 16;" :: "r"(saddr), "l"(gptr));
}
#define CP_COMMIT() asm volatile("cp.async.commit_group;" ::: "memory")
#define CP_WAIT1()  asm volatile("cp.async.wait_group 1;" ::: "memory")

__device__ __forceinline__ void mma_f16(float* c, uint32_t a0, uint32_t a1, uint32_t a2, uint32_t a3,
                                        uint32_t b0, uint32_t b1) {
    asm volatile("mma.sync.aligned.m16n8k16.row.col.f32.f16.f16.f32 "
        "{%0,%1,%2,%3}, {%4,%5,%6,%7}, {%8,%9}, {%0,%1,%2,%3};"
        : "+f"(c[0]), "+f"(c[1]), "+f"(c[2]), "+f"(c[3])
        : "r"(a0), "r"(a1), "r"(a2), "r"(a3), "r"(b0), "r"(b1));
}
__device__ __forceinline__ uint32_t pack_h2(float lo, float hi) {
    __half2 h = __floats2half2_rn(lo, hi);
    return *(uint32_t*)&h;
}

// ---------------- setup: discretization (fp64) ----------------
__global__ void setup_kernel(const float* __restrict__ Lre, const float* __restrict__ Lim,
                             const float* __restrict__ logdt)
{
    int p = blockIdx.x * blockDim.x + threadIdx.x;
    if (p >= PD) return;
    double dt  = exp((double)logdt[p]);
    double lr  = (double)Lre[p], li = (double)Lim[p];
    double mag = exp(lr * dt);
    double ang = li * dt;
    double ar  = mag * cos(ang);
    double ai  = mag * sin(ang);
    double den = lr * lr + li * li;
    double cr  = ((ar - 1.0) * lr + ai * li) / den;
    double ci  = (ai * lr - (ar - 1.0) * li) / den;
    g_Abar_re[p] = (float)ar; g_Abar_im[p] = (float)ai;
    g_coef_re[p] = (float)cr; g_coef_im[p] = (float)ci;
    double sr = ar, si = ai;
    #pragma unroll
    for (int i = 0; i < 6; i++) {   // Abar^64
        double nr = sr * sr - si * si;
        double ni = 2.0 * sr * si;
        sr = nr; si = ni;
    }
    g_AS_re[p] = (float)sr; g_AS_im[p] = (float)si;
}

// Bbar: 4 h per thread; rows interleaved (2p=re, 2p+1=im)
__global__ void build_bbar(const float* __restrict__ Bre, const float* __restrict__ Bim)
{
    int u = blockIdx.x * blockDim.x + threadIdx.x;
    if (u >= PD * HD / 4) return;
    int p = u / (HD / 4);
    int h0 = (u % (HD / 4)) * 4;
    float4 br = *(const float4*)(Bre + (size_t)p * HD + h0);
    float4 bi = *(const float4*)(Bim + (size_t)p * HD + h0);
    float cr = g_coef_re[p], ci = g_coef_im[p];
    uint32_t re[2], im[2];
    re[0] = pack_h2(BSCALE * (cr * br.x - ci * bi.x), BSCALE * (cr * br.y - ci * bi.y));
    re[1] = pack_h2(BSCALE * (cr * br.z - ci * bi.z), BSCALE * (cr * br.w - ci * bi.w));
    im[0] = pack_h2(BSCALE * (cr * bi.x + ci * br.x), BSCALE * (cr * bi.y + ci * br.y));
    im[1] = pack_h2(BSCALE * (cr * bi.z + ci * br.z), BSCALE * (cr * bi.w + ci * br.w));
    *(uint2*)(g_Bbar + (size_t)(2 * p) * HD + h0)     = *(uint2*)re;
    *(uint2*)(g_Bbar + (size_t)(2 * p + 1) * HD + h0) = *(uint2*)im;
}

// Cf: 4 p per thread; cols interleaved
__global__ void build_cfused(const float* __restrict__ Cre, const float* __restrict__ Cim)
{
    int u = blockIdx.x * blockDim.x + threadIdx.x;
    if (u >= HD * PD / 4) return;
    int h = u / (PD / 4);
    int p0 = (u % (PD / 4)) * 4;
    float4 cr = *(const float4*)(Cre + (size_t)h * PD + p0);
    float4 ci = *(const float4*)(Cim + (size_t)h * PD + p0);
    uint32_t o[4];
    o[0] = pack_h2(cr.x, -ci.x); o[1] = pack_h2(cr.y, -ci.y);
    o[2] = pack_h2(cr.z, -ci.z); o[3] = pack_h2(cr.w, -ci.w);
    *(uint4*)(g_Cf + (size_t)h * N1 + 2 * p0) = *(uint4*)o;
}

// ---------------- mma.sync fp16 GEMM: C[M,CN] = A[M,K] @ B[N,K]^T ----------------
// G1: A = x (fp32, converted in-loader), B=g_Bbar, C=g_Buh fp16 (scaled)
// !G1: A=g_xsh (fp16), B=g_Cf, C=out fp32 (epilogue 2*acc + x*(1+D))
template<int K, bool G1>
__global__ __launch_bounds__(256)
void gemm_mma(const float* __restrict__ Axf, float* __restrict__ Cout,
              const float* __restrict__ xres, const float* __restrict__ Dp)
{
    const __half* Ah = G1 ? (const __half*)nullptr : g_xsh;
    const __half* B  = G1 ? g_Bbar : g_Cf;
    const int CN = G1 ? N1 : HD;

    extern __shared__ __half smh[];
    const uint32_t sbase = smem_u32(smh);
    const int tid  = threadIdx.x;
    const int wid  = tid >> 5;
    const int lane = tid & 31;
    const int g = lane >> 2, t = lane & 3;
    const int warp_m = (wid & 1) * 64;
    const int warp_n = (wid >> 1) * 64;
    const int bm = blockIdx.y * BM;
    const int bn = blockIdx.x * BN;

    const int lrow = tid >> 3;            // 0..31
    const int lseg = (tid & 7) * 8;       // element offset within row (8 elems = 16B fp16 / 32B fp32)
    const __half* Bg = B + (size_t)(bn + lrow) * K + lseg;
    const uint32_t sAo = (uint32_t)(lrow * ASTRH + lseg) * 2;

    // A source pointers
    const float*  Agf = G1 ? (Axf + (size_t)(bm + lrow) * K + lseg) : nullptr;
    const __half* Agh = G1 ? nullptr : (Ah + (size_t)(bm + lrow) * K + lseg);

    float acc[4][8][4];
    #pragma unroll
    for (int i = 0; i < 4; i++)
        #pragma unroll
        for (int j = 0; j < 8; j++)
            #pragma unroll
            for (int q = 0; q < 4; q++) acc[i][j][q] = 0.f;

    constexpr int NCH = K / BK;

    // B stage loader (cp.async)
    auto load_B = [&](int st, int k0) {
        const uint32_t sb = sbase + (uint32_t)(st * STGH * 2) + (uint32_t)(ASTGH * 2) + sAo;
        #pragma unroll
        for (int i = 0; i < 8; i++)
            cp16(sb + i * 32 * ASTRH * 2, Bg + k0 + (size_t)i * 32 * K);
    };
    // A stage: fp16 path (cp.async) for GEMM2
    auto load_A_h = [&](int st, int k0) {
        const uint32_t sa = sbase + (uint32_t)(st * STGH * 2) + sAo;
        #pragma unroll
        for (int i = 0; i < 4; i++)
            cp16(sa + i * 32 * ASTRH * 2, Agh + k0 + (size_t)i * 32 * K);
    };
    // A stage: fp32 path for GEMM1 — LDG into regs, pack+STS later
    float4 xr[4][2];
    auto ldg_A_f = [&](int k0) {
        #pragma unroll
        for (int i = 0; i < 4; i++) {
            const float* p = Agf + k0 + (size_t)i * 32 * K;
            xr[i][0] = *(const float4*)(p);
            xr[i][1] = *(const float4*)(p + 4);
        }
    };
    auto sts_A_f = [&](int st) {
        const uint32_t sa = sbase + (uint32_t)(st * STGH * 2) + sAo;
        #pragma unroll
        for (int i = 0; i < 4; i++) {
            uint32_t o[4];
            o[0] = pack_h2(xr[i][0].x, xr[i][0].y);
            o[1] = pack_h2(xr[i][0].z, xr[i][0].w);
            o[2] = pack_h2(xr[i][1].x, xr[i][1].y);
            o[3] = pack_h2(xr[i][1].z, xr[i][1].w);
            asm volatile("st.shared.v4.b32 [%0], {%1,%2,%3,%4};"
                :: "r"(sa + i * 32 * ASTRH * 2), "r"(o[0]), "r"(o[1]), "r"(o[2]), "r"(o[3]) : "memory");
        }
    };

    // prologue
    if (G1) {
        ldg_A_f(0);      sts_A_f(0);
        ldg_A_f(BK);     sts_A_f(1);
    } else {
        load_A_h(0, 0);
        load_A_h(1, BK);
    }
    load_B(0, 0);  CP_COMMIT();
    load_B(1, BK); CP_COMMIT();

    for (int kc = 0; kc < NCH; kc++) {
        CP_WAIT1();
        __syncthreads();
        const bool pre = (kc + 2 < NCH);
        if (pre) {
            if (G1) ldg_A_f((kc + 2) * BK);          // LDG early: covered by compute below
            else    load_A_h((kc + 2) % NST, (kc + 2) * BK);
            load_B((kc + 2) % NST, (kc + 2) * BK);
        }
        CP_COMMIT();

        const int st = kc % NST;
        const __half* As_s = smh + st * STGH + (warp_m + g) * ASTRH;
        const __half* Bs_s = smh + st * STGH + ASTGH + (warp_n + g) * ASTRH;
        #pragma unroll
        for (int kk = 0; kk < 4; kk++) {
            const int k = kk * 16 + 2 * t;
            uint32_t a[4][4];
            #pragma unroll
            for (int i = 0; i < 4; i++) {
                const __half* ap = As_s + i * 16 * ASTRH + k;
                a[i][0] = *(const uint32_t*)(ap);
                a[i][1] = *(const uint32_t*)(ap + 8 * ASTRH);
                a[i][2] = *(const uint32_t*)(ap + 8);
                a[i][3] = *(const uint32_t*)(ap + 8 * ASTRH + 8);
            }
            uint32_t b[8][2];
            #pragma unroll
            for (int j = 0; j < 8; j++) {
                const __half* bp = Bs_s + j * 8 * ASTRH + k;
                b[j][0] = *(const uint32_t*)(bp);
                b[j][1] = *(const uint32_t*)(bp + 8);
            }
            #pragma unroll
            for (int i = 0; i < 4; i++)
                #pragma unroll
                for (int j = 0; j < 8; j++)
                    mma_f16(acc[i][j], a[i][0], a[i][1], a[i][2], a[i][3], b[j][0], b[j][1]);
        }
        if (G1 && pre) sts_A_f((kc + 2) % NST);      // LDG latency fully covered by compute
        __syncthreads();
    }

    #pragma unroll
    for (int i = 0; i < 4; i++) {
        const int row = bm + warp_m + i * 16 + g;
        #pragma unroll
        for (int j = 0; j < 8; j++) {
            const int col = bn + warp_n + j * 8 + 2 * t;
            if (G1) {
                *(uint32_t*)(g_Buh + (size_t)row * N1 + col)       = pack_h2(acc[i][j][0], acc[i][j][1]);
                *(uint32_t*)(g_Buh + (size_t)(row + 8) * N1 + col) = pack_h2(acc[i][j][2], acc[i][j][3]);
            } else {
                float* cp0 = Cout + (size_t)row * CN + col;
                float* cp1 = Cout + (size_t)(row + 8) * CN + col;
                const float* xp0 = xres + (size_t)row * HD + col;
                const float* xp1 = xres + (size_t)(row + 8) * HD + col;
                float2 dv = *(const float2*)(Dp + col);
                float2 x0 = *(const float2*)xp0;
                float2 x1 = *(const float2*)xp1;
                float2 v0, v1;
                v0.x = 2.f * acc[i][j][0] + x0.x * (1.f + dv.x);
                v0.y = 2.f * acc[i][j][1] + x0.y * (1.f + dv.y);
                v1.x = 2.f * acc[i][j][2] + x1.x * (1.f + dv.x);
                v1.y = 2.f * acc[i][j][3] + x1.y * (1.f + dv.y);
                *(float2*)cp0 = v0;
                *(float2*)cp1 = v1;
            }
        }
    }
}

// ---------------- chunked scan (fp16 interleaved Bu; carries BSCALE) ----------------
__global__ __launch_bounds__(256) void scan_phase1()
{
    int p = blockIdx.y * blockDim.x + threadIdx.x;
    int c = blockIdx.x;
    float Ar = g_Abar_re[p], Ai = g_Abar_im[p];
    float hr = 0.f, hi = 0.f;
    const __half* bu = g_Buh + (size_t)c * CHUNK * N1 + 2 * p;
    #pragma unroll 4
    for (int i = 0; i < CHUNK; i++) {
        float2 b = __half22float2(*(const __half2*)(bu + i * N1));
        float br = b.x * BSCALE_INV, bi = b.y * BSCALE_INV;
        float nr = fmaf(Ar, hr, fmaf(-Ai, hi, br));
        float ni = fmaf(Ar, hi, fmaf(Ai, hr, bi));
        hr = nr; hi = ni;
    }
    g_E_re[c * PD + p] = hr;
    g_E_im[c * PD + p] = hi;
}

__global__ __launch_bounds__(256) void scan_phase2()
{
    int p = blockIdx.x * blockDim.x + threadIdx.x;
    float Ar = g_AS_re[p], Ai = g_AS_im[p];
    float pr = 0.f, pi = 0.f;
    for (int c = 0; c < NCHUNK; c++) {
        g_pref_re[c * PD + p] = pr;
        g_pref_im[c * PD + p] = pi;
        float er = g_E_re[c * PD + p], ei = g_E_im[c * PD + p];
        float nr = fmaf(Ar, pr, fmaf(-Ai, pi, er));
        float ni = fmaf(Ar, pi, fmaf(Ai, pr, ei));
        pr = nr; pi = ni;
    }
}

__global__ __launch_bounds__(256) void scan_phase3()
{
    int p = blockIdx.y * blockDim.x + threadIdx.x;
    int c = blockIdx.x;
    float Ar = g_Abar_re[p], Ai = g_Abar_im[p];
    float hr = g_pref_re[c * PD + p];
    float hi = g_pref_im[c * PD + p];
    const __half* bu = g_Buh + (size_t)c * CHUNK * N1 + 2 * p;
    __half*       xs = g_xsh + (size_t)c * CHUNK * N1 + 2 * p;
    #pragma unroll 4
    for (int i = 0; i < CHUNK; i++) {
        float2 b = __half22float2(*(const __half2*)(bu + i * N1));
        float br = b.x * BSCALE_INV, bi = b.y * BSCALE_INV;
        float nr = fmaf(Ar, hr, fmaf(-Ai, hi, br));
        float ni = fmaf(Ar, hi, fmaf(Ai, hr, bi));
        hr = nr; hi = ni;
        *(uint32_t*)(xs + i * N1) = pack_h2(hr, hi);
    }
}

// ---------------- LayerNorm (in place, float4) ----------------
__global__ __launch_bounds__(256) void ln_kernel(float* __restrict__ out,
                                                 const float* __restrict__ gamma,
                                                 const float* __restrict__ beta)
{
    __shared__ float sh_s[8], sh_s2[8], sh_mr[2];
    int row = blockIdx.x;
    float* r = out + (size_t)row * HD;
    int tid = threadIdx.x;
    float4 v = *(const float4*)(r + tid * 4);
    float s  = v.x + v.y + v.z + v.w;
    float s2 = fmaf(v.x, v.x, fmaf(v.y, v.y, fmaf(v.z, v.z, v.w * v.w)));
    #pragma unroll
    for (int o = 16; o > 0; o >>= 1) {
        s  += __shfl_down_sync(0xffffffffu, s,  o);
        s2 += __shfl_down_sync(0xffffffffu, s2, o);
    }
    if ((tid & 31) == 0) { sh_s[tid >> 5] = s; sh_s2[tid >> 5] = s2; }
    __syncthreads();
    if (tid == 0) {
        float ts = 0.f, ts2 = 0.f;
        #pragma unroll
        for (int w = 0; w < 8; w++) { ts += sh_s[w]; ts2 += sh_s2[w]; }
        float mean = ts * (1.f / HD);
        float var  = ts2 * (1.f / HD) - mean * mean;
        sh_mr[0] = mean;
        sh_mr[1] = rsqrtf(var + 1e-5f);
    }
    __syncthreads();
    float mean = sh_mr[0], rstd = sh_mr[1];
    float4 gv = *(const float4*)(gamma + tid * 4);
    float4 bv = *(const float4*)(beta + tid * 4);
    float4 o;
    o.x = (v.x - mean) * rstd * gv.x + bv.x;
    o.y = (v.y - mean) * rstd * gv.y + bv.y;
    o.z = (v.z - mean) * rstd * gv.z + bv.z;
    o.w = (v.w - mean) * rstd * gv.w + bv.w;
    *(float4*)(r + tid * 4) = o;
}

// ---------------- launch ----------------
extern "C" void kernel_launch(void* const* d_in, const int* in_sizes, int n_in,
                              void* d_out, int out_size)
{
    const float* x     = (const float*)d_in[0];
    const float* Lre   = (const float*)d_in[1];
    const float* Lim   = (const float*)d_in[2];
    const float* Bre   = (const float*)d_in[3];
    const float* Bim   = (const float*)d_in[4];
    const float* Cre   = (const float*)d_in[5];
    const float* Cim   = (const float*)d_in[6];
    const float* D     = (const float*)d_in[7];
    const float* logdt = (const float*)d_in[8];
    const float* gamma = (const float*)d_in[9];
    const float* beta  = (const float*)d_in[10];
    float* out = (float*)d_out;

    cudaFuncSetAttribute(gemm_mma<HD, true>,  cudaFuncAttributeMaxDynamicSharedMemorySize, SMEM_BYTES);
    cudaFuncSetAttribute(gemm_mma<N1, false>, cudaFuncAttributeMaxDynamicSharedMemorySize, SMEM_BYTES);

    setup_kernel<<<4, 256>>>(Lre, Lim, logdt);
    build_bbar<<<PD * HD / 4 / 256, 256>>>(Bre, Bim);
    build_cfused<<<HD * PD / 4 / 256, 256>>>(Cre, Cim);

    // Bu = x @ Bbar^T   (M=8192, N=2048, K=1024); A converted fp32->fp16 in-loader
    gemm_mma<HD, true><<<dim3(N1 / BN, LQ / BM), 256, SMEM_BYTES>>>(x, nullptr, nullptr, nullptr);

    scan_phase1<<<dim3(NCHUNK, PD / 256), 256>>>();
    scan_phase2<<<PD / 256, 256>>>();
    scan_phase3<<<dim3(NCHUNK, PD / 256), 256>>>();

    // out = 2*Re(xs @ C^T) + x*(1+D)   (M=8192, N=1024, K=2048)
    gemm_mma<N1, false><<<dim3(HD / BN, LQ / BM), 256, SMEM_BYTES>>>(nullptr, out, x, D);

    ln_kernel<<<LQ, 256>>>(out, gamma, beta);
}

// round 15
// speedup vs baseline: 1.0539x; 1.0539x over previous
#include <cuda_runtime.h>
#include <cuda_fp16.h>
#include <math.h>
#include <stdint.h>

#define LQ 8192
#define HD 1024
#define PD 1024
#define N1 2048
#define NCHUNK 128
#define CHUNK 64

// ---- GEMM tile config (fp16 m16n8k16) ----
#define BM 128
#define BN 256
#define BK 64
#define NST 3
#define ASTRH 72
#define ASTGH (128 * ASTRH)
#define STGH (384 * ASTRH)
#define SMEM_BYTES (NST * STGH * 2)       // 165888
#define BSCALE 1024.0f
#define BSCALE_INV (1.0f / 1024.0f)

// prep_kernel grid partition
#define PREP_X_BLOCKS (LQ * HD / 8 / 256)          // 4096
#define PREP_BB_BLOCKS (PD * HD / 4 / 256)         // 1024
#define PREP_CF_BLOCKS (HD * PD / 4 / 256)         // 1024

// ---------------- device scratch ----------------
// complex-interleaved layouts: Bu/xs columns [re0 im0 ...]; Bbar rows 2p/2p+1; Cf cols 2p/2p+1
__device__ __half g_xh[LQ * HD];          // x in fp16
__device__ __half g_Bbar[N1 * HD];        // row 2p = re_p, row 2p+1 = im_p (scaled by 1024)
__device__ __half g_Cf[HD * N1];          // col 2p = C_re, col 2p+1 = -C_im
__device__ __half g_xsh[LQ * N1];         // scan output fp16, interleaved
__device__ __half g_Buh[LQ * N1];         // fp16 scan input (scaled), interleaved
__device__ float g_Abar_re[PD], g_Abar_im[PD];
__device__ float g_coef_re[PD], g_coef_im[PD];
__device__ float g_AS_re[PD],   g_AS_im[PD];
__device__ float g_E_re[NCHUNK * PD], g_E_im[NCHUNK * PD];
__device__ float g_pref_re[NCHUNK * PD], g_pref_im[NCHUNK * PD];

// ---------------- helpers ----------------
__device__ __forceinline__ uint32_t smem_u32(const void* p) {
    uint32_t a;
    asm("{ .reg .u64 t; cvta.to.shared.u64 t, %1; cvt.u32.u64 %0, t; }" : "=r"(a) : "l"(p));
    return a;
}
__device__ __forceinline__ void cp16(uint32_t saddr, const void* gptr) {
    asm volatile("cp.async.ca.shared.global [%0], [%1], 16;" :: "r"(saddr), "l"(gptr));
}
#define CP_COMMIT() asm volatile("cp.async.commit_group;" ::: "memory")
#define CP_WAIT1()  asm volatile("cp.async.wait_group 1;" ::: "memory")

__device__ __forceinline__ void mma_f16(float* c, uint32_t a0, uint32_t a1, uint32_t a2, uint32_t a3,
                                        uint32_t b0, uint32_t b1) {
    asm volatile("mma.sync.aligned.m16n8k16.row.col.f32.f16.f16.f32 "
        "{%0,%1,%2,%3}, {%4,%5,%6,%7}, {%8,%9}, {%0,%1,%2,%3};"
        : "+f"(c[0]), "+f"(c[1]), "+f"(c[2]), "+f"(c[3])
        : "r"(a0), "r"(a1), "r"(a2), "r"(a3), "r"(b0), "r"(b1));
}
__device__ __forceinline__ uint32_t pack_h2(float lo, float hi) {
    __half2 h = __floats2half2_rn(lo, hi);
    return *(uint32_t*)&h;
}

// ---------------- setup: discretization (fp64) ----------------
__global__ void setup_kernel(const float* __restrict__ Lre, const float* __restrict__ Lim,
                             const float* __restrict__ logdt)
{
    int p = blockIdx.x * blockDim.x + threadIdx.x;
    if (p >= PD) return;
    double dt  = exp((double)logdt[p]);
    double lr  = (double)Lre[p], li = (double)Lim[p];
    double mag = exp(lr * dt);
    double ang = li * dt;
    double ar  = mag * cos(ang);
    double ai  = mag * sin(ang);
    double den = lr * lr + li * li;
    double cr  = ((ar - 1.0) * lr + ai * li) / den;
    double ci  = (ai * lr - (ar - 1.0) * li) / den;
    g_Abar_re[p] = (float)ar; g_Abar_im[p] = (float)ai;
    g_coef_re[p] = (float)cr; g_coef_im[p] = (float)ci;
    double sr = ar, si = ai;
    #pragma unroll
    for (int i = 0; i < 6; i++) {   // Abar^64
        double nr = sr * sr - si * si;
        double ni = 2.0 * sr * si;
        sr = nr; si = ni;
    }
    g_AS_re[p] = (float)sr; g_AS_im[p] = (float)si;
}

// ---------------- merged prep: conv_x | build_bbar | build_cfused ----------------
__global__ __launch_bounds__(256) void prep_kernel(
    const float* __restrict__ x,
    const float* __restrict__ Bre, const float* __restrict__ Bim,
    const float* __restrict__ Cre, const float* __restrict__ Cim)
{
    int bid = blockIdx.x;
    int tid = threadIdx.x;
    if (bid < PREP_X_BLOCKS) {
        // conv_x: 8 elems/thread
        int idx = (bid * 256 + tid) * 8;
        float4 v0 = *(const float4*)(x + idx);
        float4 v1 = *(const float4*)(x + idx + 4);
        uint32_t o[4];
        o[0] = pack_h2(v0.x, v0.y); o[1] = pack_h2(v0.z, v0.w);
        o[2] = pack_h2(v1.x, v1.y); o[3] = pack_h2(v1.z, v1.w);
        *(uint4*)(g_xh + idx) = *(uint4*)o;
    } else if (bid < PREP_X_BLOCKS + PREP_BB_BLOCKS) {
        // build_bbar: 4 h/thread, rows interleaved (2p=re, 2p+1=im)
        int u = (bid - PREP_X_BLOCKS) * 256 + tid;
        int p = u / (HD / 4);
        int h0 = (u % (HD / 4)) * 4;
        float4 br = *(const float4*)(Bre + (size_t)p * HD + h0);
        float4 bi = *(const float4*)(Bim + (size_t)p * HD + h0);
        float cr = g_coef_re[p], ci = g_coef_im[p];
        uint32_t re[2], im[2];
        re[0] = pack_h2(BSCALE * (cr * br.x - ci * bi.x), BSCALE * (cr * br.y - ci * bi.y));
        re[1] = pack_h2(BSCALE * (cr * br.z - ci * bi.z), BSCALE * (cr * br.w - ci * bi.w));
        im[0] = pack_h2(BSCALE * (cr * bi.x + ci * br.x), BSCALE * (cr * bi.y + ci * br.y));
        im[1] = pack_h2(BSCALE * (cr * bi.z + ci * br.z), BSCALE * (cr * bi.w + ci * br.w));
        *(uint2*)(g_Bbar + (size_t)(2 * p) * HD + h0)     = *(uint2*)re;
        *(uint2*)(g_Bbar + (size_t)(2 * p + 1) * HD + h0) = *(uint2*)im;
    } else {
        // build_cfused: 4 p/thread, cols interleaved
        int u = (bid - PREP_X_BLOCKS - PREP_BB_BLOCKS) * 256 + tid;
        int h = u / (PD / 4);
        int p0 = (u % (PD / 4)) * 4;
        float4 cr = *(const float4*)(Cre + (size_t)h * PD + p0);
        float4 ci = *(const float4*)(Cim + (size_t)h * PD + p0);
        uint32_t o[4];
        o[0] = pack_h2(cr.x, -ci.x); o[1] = pack_h2(cr.y, -ci.y);
        o[2] = pack_h2(cr.z, -ci.z); o[3] = pack_h2(cr.w, -ci.w);
        *(uint4*)(g_Cf + (size_t)h * N1 + 2 * p0) = *(uint4*)o;
    }
}

// ---------------- mma.sync fp16 GEMM: C[M,CN] = A[M,K] @ B[N,K]^T ----------------
// G1: A=g_xh, B=g_Bbar, C=g_Buh fp16 (scaled)
// !G1: A=g_xsh, B=g_Cf, C=out fp32 (epilogue 2*acc + xh*(1+D), residual read fp16)
template<int K, bool G1>
__global__ __launch_bounds__(256)
void gemm_mma(float* __restrict__ Cout, const float* __restrict__ Dp)
{
    const __half* A = G1 ? g_xh : g_xsh;
    const __half* B = G1 ? g_Bbar : g_Cf;
    const int CN = G1 ? N1 : HD;

    extern __shared__ __half smh[];
    const uint32_t sbase = smem_u32(smh);
    const int tid  = threadIdx.x;
    const int wid  = tid >> 5;
    const int lane = tid & 31;
    const int g = lane >> 2, t = lane & 3;
    const int warp_m = (wid & 1) * 64;
    const int warp_n = (wid >> 1) * 64;
    const int bm = blockIdx.y * BM;
    const int bn = blockIdx.x * BN;

    const int lrow = tid >> 3;
    const int lseg = (tid & 7) * 8;
    const __half* Ag = A + (size_t)(bm + lrow) * K + lseg;
    const __half* Bg = B + (size_t)(bn + lrow) * K + lseg;
    const uint32_t sAo = (uint32_t)(lrow * ASTRH + lseg) * 2;

    float acc[4][8][4];
    #pragma unroll
    for (int i = 0; i < 4; i++)
        #pragma unroll
        for (int j = 0; j < 8; j++)
            #pragma unroll
            for (int q = 0; q < 4; q++) acc[i][j][q] = 0.f;

    constexpr int NCH = K / BK;

    auto load_stage = [&](int st, int k0) {
        const uint32_t sa = sbase + (uint32_t)(st * STGH * 2) + sAo;
        const uint32_t sb = sa + (uint32_t)(ASTGH * 2);
        #pragma unroll
        for (int i = 0; i < 4; i++)
            cp16(sa + i * 32 * ASTRH * 2, Ag + k0 + (size_t)i * 32 * K);
        #pragma unroll
        for (int i = 0; i < 8; i++)
            cp16(sb + i * 32 * ASTRH * 2, Bg + k0 + (size_t)i * 32 * K);
    };

    load_stage(0, 0);  CP_COMMIT();
    load_stage(1, BK); CP_COMMIT();

    for (int kc = 0; kc < NCH; kc++) {
        CP_WAIT1();
        __syncthreads();
        if (kc + 2 < NCH) load_stage((kc + 2) % NST, (kc + 2) * BK);
        CP_COMMIT();

        const int st = kc % NST;
        const __half* As_s = smh + st * STGH + (warp_m + g) * ASTRH;
        const __half* Bs_s = smh + st * STGH + ASTGH + (warp_n + g) * ASTRH;
        #pragma unroll
        for (int kk = 0; kk < 4; kk++) {
            const int k = kk * 16 + 2 * t;
            uint32_t a[4][4];
            #pragma unroll
            for (int i = 0; i < 4; i++) {
                const __half* ap = As_s + i * 16 * ASTRH + k;
                a[i][0] = *(const uint32_t*)(ap);
                a[i][1] = *(const uint32_t*)(ap + 8 * ASTRH);
                a[i][2] = *(const uint32_t*)(ap + 8);
                a[i][3] = *(const uint32_t*)(ap + 8 * ASTRH + 8);
            }
            uint32_t b[8][2];
            #pragma unroll
            for (int j = 0; j < 8; j++) {
                const __half* bp = Bs_s + j * 8 * ASTRH + k;
                b[j][0] = *(const uint32_t*)(bp);
                b[j][1] = *(const uint32_t*)(bp + 8);
            }
            #pragma unroll
            for (int i = 0; i < 4; i++)
                #pragma unroll
                for (int j = 0; j < 8; j++)
                    mma_f16(acc[i][j], a[i][0], a[i][1], a[i][2], a[i][3], b[j][0], b[j][1]);
        }
        __syncthreads();
    }

    #pragma unroll
    for (int i = 0; i < 4; i++) {
        const int row = bm + warp_m + i * 16 + g;
        #pragma unroll
        for (int j = 0; j < 8; j++) {
            const int col = bn + warp_n + j * 8 + 2 * t;
            if (G1) {
                *(uint32_t*)(g_Buh + (size_t)row * N1 + col)       = pack_h2(acc[i][j][0], acc[i][j][1]);
                *(uint32_t*)(g_Buh + (size_t)(row + 8) * N1 + col) = pack_h2(acc[i][j][2], acc[i][j][3]);
            } else {
                float* cp0 = Cout + (size_t)row * CN + col;
                float* cp1 = Cout + (size_t)(row + 8) * CN + col;
                float2 x0 = __half22float2(*(const __half2*)(g_xh + (size_t)row * HD + col));
                float2 x1 = __half22float2(*(const __half2*)(g_xh + (size_t)(row + 8) * HD + col));
                float2 dv = *(const float2*)(Dp + col);
                float2 v0, v1;
                v0.x = 2.f * acc[i][j][0] + x0.x * (1.f + dv.x);
                v0.y = 2.f * acc[i][j][1] + x0.y * (1.f + dv.y);
                v1.x = 2.f * acc[i][j][2] + x1.x * (1.f + dv.x);
                v1.y = 2.f * acc[i][j][3] + x1.y * (1.f + dv.y);
                *(float2*)cp0 = v0;
                *(float2*)cp1 = v1;
            }
        }
    }
}

// ---------------- chunked scan (fp16 interleaved Bu; carries BSCALE) ----------------
__global__ __launch_bounds__(256) void scan_phase1()
{
    int p = blockIdx.y * blockDim.x + threadIdx.x;
    int c = blockIdx.x;
    float Ar = g_Abar_re[p], Ai = g_Abar_im[p];
    float hr = 0.f, hi = 0.f;
    const __half* bu = g_Buh + (size_t)c * CHUNK * N1 + 2 * p;
    #pragma unroll 4
    for (int i = 0; i < CHUNK; i++) {
        float2 b = __half22float2(*(const __half2*)(bu + i * N1));
        float br = b.x * BSCALE_INV, bi = b.y * BSCALE_INV;
        float nr = fmaf(Ar, hr, fmaf(-Ai, hi, br));
        float ni = fmaf(Ar, hi, fmaf(Ai, hr, bi));
        hr = nr; hi = ni;
    }
    g_E_re[c * PD + p] = hr;
    g_E_im[c * PD + p] = hi;
}

__global__ __launch_bounds__(256) void scan_phase2()
{
    int p = blockIdx.x * blockDim.x + threadIdx.x;
    float Ar = g_AS_re[p], Ai = g_AS_im[p];
    float pr = 0.f, pi = 0.f;
    for (int c = 0; c < NCHUNK; c++) {
        g_pref_re[c * PD + p] = pr;
        g_pref_im[c * PD + p] = pi;
        float er = g_E_re[c * PD + p], ei = g_E_im[c * PD + p];
        float nr = fmaf(Ar, pr, fmaf(-Ai, pi, er));
        float ni = fmaf(Ar, pi, fmaf(Ai, pr, ei));
        pr = nr; pi = ni;
    }
}

__global__ __launch_bounds__(256) void scan_phase3()
{
    int p = blockIdx.y * blockDim.x + threadIdx.x;
    int c = blockIdx.x;
    float Ar = g_Abar_re[p], Ai = g_Abar_im[p];
    float hr = g_pref_re[c * PD + p];
    float hi = g_pref_im[c * PD + p];
    const __half* bu = g_Buh + (size_t)c * CHUNK * N1 + 2 * p;
    __half*       xs = g_xsh + (size_t)c * CHUNK * N1 + 2 * p;
    #pragma unroll 4
    for (int i = 0; i < CHUNK; i++) {
        float2 b = __half22float2(*(const __half2*)(bu + i * N1));
        float br = b.x * BSCALE_INV, bi = b.y * BSCALE_INV;
        float nr = fmaf(Ar, hr, fmaf(-Ai, hi, br));
        float ni = fmaf(Ar, hi, fmaf(Ai, hr, bi));
        hr = nr; hi = ni;
        *(uint32_t*)(xs + i * N1) = pack_h2(hr, hi);
    }
}

// ---------------- LayerNorm (in place, float4) ----------------
__global__ __launch_bounds__(256) void ln_kernel(float* __restrict__ out,
                                                 const float* __restrict__ gamma,
                                                 const float* __restrict__ beta)
{
    __shared__ float sh_s[8], sh_s2[8], sh_mr[2];
    int row = blockIdx.x;
    float* r = out + (size_t)row * HD;
    int tid = threadIdx.x;
    float4 v = *(const float4*)(r + tid * 4);
    float s  = v.x + v.y + v.z + v.w;
    float s2 = fmaf(v.x, v.x, fmaf(v.y, v.y, fmaf(v.z, v.z, v.w * v.w)));
    #pragma unroll
    for (int o = 16; o > 0; o >>= 1) {
        s  += __shfl_down_sync(0xffffffffu, s,  o);
        s2 += __shfl_down_sync(0xffffffffu, s2, o);
    }
    if ((tid & 31) == 0) { sh_s[tid >> 5] = s; sh_s2[tid >> 5] = s2; }
    __syncthreads();
    if (tid == 0) {
        float ts = 0.f, ts2 = 0.f;
        #pragma unroll
        for (int w = 0; w < 8; w++) { ts += sh_s[w]; ts2 += sh_s2[w]; }
        float mean = ts * (1.f / HD);
        float var  = ts2 * (1.f / HD) - mean * mean;
        sh_mr[0] = mean;
        sh_mr[1] = rsqrtf(var + 1e-5f);
    }
    __syncthreads();
    float mean = sh_mr[0], rstd = sh_mr[1];
    float4 gv = *(const float4*)(gamma + tid * 4);
    float4 bv = *(const float4*)(beta + tid * 4);
    float4 o;
    o.x = (v.x - mean) * rstd * gv.x + bv.x;
    o.y = (v.y - mean) * rstd * gv.y + bv.y;
    o.z = (v.z - mean) * rstd * gv.z + bv.z;
    o.w = (v.w - mean) * rstd * gv.w + bv.w;
    *(float4*)(r + tid * 4) = o;
}

// ---------------- launch ----------------
extern "C" void kernel_launch(void* const* d_in, const int* in_sizes, int n_in,
                              void* d_out, int out_size)
{
    const float* x     = (const float*)d_in[0];
    const float* Lre   = (const float*)d_in[1];
    const float* Lim   = (const float*)d_in[2];
    const float* Bre   = (const float*)d_in[3];
    const float* Bim   = (const float*)d_in[4];
    const float* Cre   = (const float*)d_in[5];
    const float* Cim   = (const float*)d_in[6];
    const float* D     = (const float*)d_in[7];
    const float* logdt = (const float*)d_in[8];
    const float* gamma = (const float*)d_in[9];
    const float* beta  = (const float*)d_in[10];
    float* out = (float*)d_out;

    cudaFuncSetAttribute(gemm_mma<HD, true>,  cudaFuncAttributeMaxDynamicSharedMemorySize, SMEM_BYTES);
    cudaFuncSetAttribute(gemm_mma<N1, false>, cudaFuncAttributeMaxDynamicSharedMemorySize, SMEM_BYTES);

    setup_kernel<<<4, 256>>>(Lre, Lim, logdt);
    prep_kernel<<<PREP_X_BLOCKS + PREP_BB_BLOCKS + PREP_CF_BLOCKS, 256>>>(x, Bre, Bim, Cre, Cim);

    // Bu = x @ Bbar^T   (M=8192, N=2048, K=1024), output fp16
    gemm_mma<HD, true><<<dim3(N1 / BN, LQ / BM), 256, SMEM_BYTES>>>(nullptr, nullptr);

    scan_phase1<<<dim3(NCHUNK, PD / 256), 256>>>();
    scan_phase2<<<PD / 256, 256>>>();
    scan_phase3<<<dim3(NCHUNK, PD / 256), 256>>>();

    // out = 2*Re(xs @ C^T) + x*(1+D)   (M=8192, N=1024, K=2048)
    gemm_mma<N1, false><<<dim3(HD / BN, LQ / BM), 256, SMEM_BYTES>>>(out, D);

    ln_kernel<<<LQ, 256>>>(out, gamma, beta);
}

// round 16
// speedup vs baseline: 1.0676x; 1.0130x over previous
#include <cuda_runtime.h>
#include <cuda_fp16.h>
#include <math.h>
#include <stdint.h>

#define LQ 8192
#define HD 1024
#define PD 1024
#define N1 2048
#define NCHUNK 128
#define CHUNK 64

// ---- GEMM tile config (fp16 m16n8k16) ----
#define BM 128
#define BN 256
#define BK 64
#define NST 3
#define ASTRH 72
#define ASTGH (128 * ASTRH)
#define STGH (384 * ASTRH)
#define SMEM_BYTES (NST * STGH * 2)       // 165888
#define BSCALE 1024.0f
#define BSCALE_INV (1.0f / 1024.0f)

// ---------------- device scratch ----------------
// complex-interleaved layouts: Bu/xs columns [re0 im0 ...]; Bbar rows 2p/2p+1; Cf cols 2p/2p+1
__device__ __half g_xh[LQ * HD];          // x in fp16
__device__ __half g_Bbar[N1 * HD];        // row 2p = re_p, row 2p+1 = im_p (scaled by 1024)
__device__ __half g_Cf[HD * N1];          // col 2p = C_re, col 2p+1 = -C_im
__device__ __half g_xsh[LQ * N1];         // scan output fp16, interleaved
__device__ __half g_Buh[LQ * N1];         // fp16 scan input (scaled), interleaved
__device__ float g_Abar_re[PD], g_Abar_im[PD];
__device__ float g_coef_re[PD], g_coef_im[PD];
__device__ float g_AS_re[PD],   g_AS_im[PD];
__device__ float g_E_re[NCHUNK * PD], g_E_im[NCHUNK * PD];
__device__ float g_pref_re[NCHUNK * PD], g_pref_im[NCHUNK * PD];

// ---------------- helpers ----------------
__device__ __forceinline__ uint32_t smem_u32(const void* p) {
    uint32_t a;
    asm("{ .reg .u64 t; cvta.to.shared.u64 t, %1; cvt.u32.u64 %0, t; }" : "=r"(a) : "l"(p));
    return a;
}
__device__ __forceinline__ void cp16(uint32_t saddr, const void* gptr) {
    asm volatile("cp.async.ca.shared.global [%0], [%1], 16;" :: "r"(saddr), "l"(gptr));
}
#define CP_COMMIT() asm volatile("cp.async.commit_group;" ::: "memory")
#define CP_WAIT1()  asm volatile("cp.async.wait_group 1;" ::: "memory")

__device__ __forceinline__ void mma_f16(float* c, uint32_t a0, uint32_t a1, uint32_t a2, uint32_t a3,
                                        uint32_t b0, uint32_t b1) {
    asm volatile("mma.sync.aligned.m16n8k16.row.col.f32.f16.f16.f32 "
        "{%0,%1,%2,%3}, {%4,%5,%6,%7}, {%8,%9}, {%0,%1,%2,%3};"
        : "+f"(c[0]), "+f"(c[1]), "+f"(c[2]), "+f"(c[3])
        : "r"(a0), "r"(a1), "r"(a2), "r"(a3), "r"(b0), "r"(b1));
}
__device__ __forceinline__ uint32_t pack_h2(float lo, float hi) {
    __half2 h = __floats2half2_rn(lo, hi);
    return *(uint32_t*)&h;
}

// ---------------- setup: discretization (fp64) ----------------
__global__ void setup_kernel(const float* __restrict__ Lre, const float* __restrict__ Lim,
                             const float* __restrict__ logdt)
{
    int p = blockIdx.x * blockDim.x + threadIdx.x;
    if (p >= PD) return;
    double dt  = exp((double)logdt[p]);
    double lr  = (double)Lre[p], li = (double)Lim[p];
    double mag = exp(lr * dt);
    double ang = li * dt;
    double ar  = mag * cos(ang);
    double ai  = mag * sin(ang);
    double den = lr * lr + li * li;
    double cr  = ((ar - 1.0) * lr + ai * li) / den;
    double ci  = (ai * lr - (ar - 1.0) * li) / den;
    g_Abar_re[p] = (float)ar; g_Abar_im[p] = (float)ai;
    g_coef_re[p] = (float)cr; g_coef_im[p] = (float)ci;
    double sr = ar, si = ai;
    #pragma unroll
    for (int i = 0; i < 6; i++) {   // Abar^64
        double nr = sr * sr - si * si;
        double ni = 2.0 * sr * si;
        sr = nr; si = ni;
    }
    g_AS_re[p] = (float)sr; g_AS_im[p] = (float)si;
}

// x fp32 -> fp16, 8 elems/thread
__global__ void conv_x(const float* __restrict__ x)
{
    int idx = (blockIdx.x * blockDim.x + threadIdx.x) * 8;
    if (idx >= LQ * HD) return;
    float4 v0 = *(const float4*)(x + idx);
    float4 v1 = *(const float4*)(x + idx + 4);
    uint32_t o[4];
    o[0] = pack_h2(v0.x, v0.y); o[1] = pack_h2(v0.z, v0.w);
    o[2] = pack_h2(v1.x, v1.y); o[3] = pack_h2(v1.z, v1.w);
    *(uint4*)(g_xh + idx) = *(uint4*)o;
}

// Bbar: 4 h per thread; rows interleaved (2p=re, 2p+1=im)
__global__ void build_bbar(const float* __restrict__ Bre, const float* __restrict__ Bim)
{
    int u = blockIdx.x * blockDim.x + threadIdx.x;
    if (u >= PD * HD / 4) return;
    int p = u / (HD / 4);
    int h0 = (u % (HD / 4)) * 4;
    float4 br = *(const float4*)(Bre + (size_t)p * HD + h0);
    float4 bi = *(const float4*)(Bim + (size_t)p * HD + h0);
    float cr = g_coef_re[p], ci = g_coef_im[p];
    uint32_t re[2], im[2];
    re[0] = pack_h2(BSCALE * (cr * br.x - ci * bi.x), BSCALE * (cr * br.y - ci * bi.y));
    re[1] = pack_h2(BSCALE * (cr * br.z - ci * bi.z), BSCALE * (cr * br.w - ci * bi.w));
    im[0] = pack_h2(BSCALE * (cr * bi.x + ci * br.x), BSCALE * (cr * bi.y + ci * br.y));
    im[1] = pack_h2(BSCALE * (cr * bi.z + ci * br.z), BSCALE * (cr * bi.w + ci * br.w));
    *(uint2*)(g_Bbar + (size_t)(2 * p) * HD + h0)     = *(uint2*)re;
    *(uint2*)(g_Bbar + (size_t)(2 * p + 1) * HD + h0) = *(uint2*)im;
}

// Cf: 4 p per thread; cols interleaved
__global__ void build_cfused(const float* __restrict__ Cre, const float* __restrict__ Cim)
{
    int u = blockIdx.x * blockDim.x + threadIdx.x;
    if (u >= HD * PD / 4) return;
    int h = u / (PD / 4);
    int p0 = (u % (PD / 4)) * 4;
    float4 cr = *(const float4*)(Cre + (size_t)h * PD + p0);
    float4 ci = *(const float4*)(Cim + (size_t)h * PD + p0);
    uint32_t o[4];
    o[0] = pack_h2(cr.x, -ci.x); o[1] = pack_h2(cr.y, -ci.y);
    o[2] = pack_h2(cr.z, -ci.z); o[3] = pack_h2(cr.w, -ci.w);
    *(uint4*)(g_Cf + (size_t)h * N1 + 2 * p0) = *(uint4*)o;
}

// ---------------- mma.sync fp16 GEMM: C[M,CN] = A[M,K] @ B[N,K]^T ----------------
// G1: A=g_xh, B=g_Bbar, C=g_Buh fp16 (scaled)
// !G1: A=g_xsh, B=g_Cf, C=out fp32 (epilogue 2*acc + x*(1+D), fp32 residual)
template<int K, bool G1>
__global__ __launch_bounds__(256)
void gemm_mma(float* __restrict__ Cout,
              const float* __restrict__ xres, const float* __restrict__ Dp)
{
    const __half* A = G1 ? g_xh : g_xsh;
    const __half* B = G1 ? g_Bbar : g_Cf;
    const int CN = G1 ? N1 : HD;

    extern __shared__ __half smh[];
    const uint32_t sbase = smem_u32(smh);
    const int tid  = threadIdx.x;
    const int wid  = tid >> 5;
    const int lane = tid & 31;
    const int g = lane >> 2, t = lane & 3;
    const int warp_m = (wid & 1) * 64;
    const int warp_n = (wid >> 1) * 64;
    const int bm = blockIdx.y * BM;
    const int bn = blockIdx.x * BN;

    const int lrow = tid >> 3;
    const int lseg = (tid & 7) * 8;
    const __half* Ag = A + (size_t)(bm + lrow) * K + lseg;
    const __half* Bg = B + (size_t)(bn + lrow) * K + lseg;
    const uint32_t sAo = (uint32_t)(lrow * ASTRH + lseg) * 2;

    float acc[4][8][4];
    #pragma unroll
    for (int i = 0; i < 4; i++)
        #pragma unroll
        for (int j = 0; j < 8; j++)
            #pragma unroll
            for (int q = 0; q < 4; q++) acc[i][j][q] = 0.f;

    constexpr int NCH = K / BK;

    auto load_stage = [&](int st, int k0) {
        const uint32_t sa = sbase + (uint32_t)(st * STGH * 2) + sAo;
        const uint32_t sb = sa + (uint32_t)(ASTGH * 2);
        #pragma unroll
        for (int i = 0; i < 4; i++)
            cp16(sa + i * 32 * ASTRH * 2, Ag + k0 + (size_t)i * 32 * K);
        #pragma unroll
        for (int i = 0; i < 8; i++)
            cp16(sb + i * 32 * ASTRH * 2, Bg + k0 + (size_t)i * 32 * K);
    };

    load_stage(0, 0);  CP_COMMIT();
    load_stage(1, BK); CP_COMMIT();

    for (int kc = 0; kc < NCH; kc++) {
        CP_WAIT1();
        __syncthreads();
        if (kc + 2 < NCH) load_stage((kc + 2) % NST, (kc + 2) * BK);
        CP_COMMIT();

        const int st = kc % NST;
        const __half* As_s = smh + st * STGH + (warp_m + g) * ASTRH;
        const __half* Bs_s = smh + st * STGH + ASTGH + (warp_n + g) * ASTRH;
        #pragma unroll
        for (int kk = 0; kk < 4; kk++) {
            const int k = kk * 16 + 2 * t;
            uint32_t a[4][4];
            #pragma unroll
            for (int i = 0; i < 4; i++) {
                const __half* ap = As_s + i * 16 * ASTRH + k;
                a[i][0] = *(const uint32_t*)(ap);
                a[i][1] = *(const uint32_t*)(ap + 8 * ASTRH);
                a[i][2] = *(const uint32_t*)(ap + 8);
                a[i][3] = *(const uint32_t*)(ap + 8 * ASTRH + 8);
            }
            uint32_t b[8][2];
            #pragma unroll
            for (int j = 0; j < 8; j++) {
                const __half* bp = Bs_s + j * 8 * ASTRH + k;
                b[j][0] = *(const uint32_t*)(bp);
                b[j][1] = *(const uint32_t*)(bp + 8);
            }
            #pragma unroll
            for (int i = 0; i < 4; i++)
                #pragma unroll
                for (int j = 0; j < 8; j++)
                    mma_f16(acc[i][j], a[i][0], a[i][1], a[i][2], a[i][3], b[j][0], b[j][1]);
        }
        __syncthreads();
    }

    #pragma unroll
    for (int i = 0; i < 4; i++) {
        const int row = bm + warp_m + i * 16 + g;
        #pragma unroll
        for (int j = 0; j < 8; j++) {
            const int col = bn + warp_n + j * 8 + 2 * t;
            if (G1) {
                *(uint32_t*)(g_Buh + (size_t)row * N1 + col)       = pack_h2(acc[i][j][0], acc[i][j][1]);
                *(uint32_t*)(g_Buh + (size_t)(row + 8) * N1 + col) = pack_h2(acc[i][j][2], acc[i][j][3]);
            } else {
                float* cp0 = Cout + (size_t)row * CN + col;
                float* cp1 = Cout + (size_t)(row + 8) * CN + col;
                const float* xp0 = xres + (size_t)row * HD + col;
                const float* xp1 = xres + (size_t)(row + 8) * HD + col;
                float2 dv = *(const float2*)(Dp + col);
                float2 x0 = *(const float2*)xp0;
                float2 x1 = *(const float2*)xp1;
                float2 v0, v1;
                v0.x = 2.f * acc[i][j][0] + x0.x * (1.f + dv.x);
                v0.y = 2.f * acc[i][j][1] + x0.y * (1.f + dv.y);
                v1.x = 2.f * acc[i][j][2] + x1.x * (1.f + dv.x);
                v1.y = 2.f * acc[i][j][3] + x1.y * (1.f + dv.y);
                *(float2*)cp0 = v0;
                *(float2*)cp1 = v1;
            }
        }
    }
}

// ---------------- chunked scan (fp16 interleaved Bu; carries BSCALE) ----------------
__global__ __launch_bounds__(256) void scan_phase1()
{
    int p = blockIdx.y * blockDim.x + threadIdx.x;
    int c = blockIdx.x;
    float Ar = g_Abar_re[p], Ai = g_Abar_im[p];
    float hr = 0.f, hi = 0.f;
    const __half* bu = g_Buh + (size_t)c * CHUNK * N1 + 2 * p;
    #pragma unroll 8
    for (int i = 0; i < CHUNK; i++) {
        float2 b = __half22float2(*(const __half2*)(bu + i * N1));
        float br = b.x * BSCALE_INV, bi = b.y * BSCALE_INV;
        float nr = fmaf(Ar, hr, fmaf(-Ai, hi, br));
        float ni = fmaf(Ar, hi, fmaf(Ai, hr, bi));
        hr = nr; hi = ni;
    }
    g_E_re[c * PD + p] = hr;
    g_E_im[c * PD + p] = hi;
}

__global__ __launch_bounds__(128) void scan_phase2()
{
    int p = blockIdx.x * blockDim.x + threadIdx.x;
    float Ar = g_AS_re[p], Ai = g_AS_im[p];
    float pr = 0.f, pi = 0.f;
    for (int c = 0; c < NCHUNK; c++) {
        g_pref_re[c * PD + p] = pr;
        g_pref_im[c * PD + p] = pi;
        float er = g_E_re[c * PD + p], ei = g_E_im[c * PD + p];
        float nr = fmaf(Ar, pr, fmaf(-Ai, pi, er));
        float ni = fmaf(Ar, pi, fmaf(Ai, pr, ei));
        pr = nr; pi = ni;
    }
}

__global__ __launch_bounds__(256) void scan_phase3()
{
    int p = blockIdx.y * blockDim.x + threadIdx.x;
    int c = blockIdx.x;
    float Ar = g_Abar_re[p], Ai = g_Abar_im[p];
    float hr = g_pref_re[c * PD + p];
    float hi = g_pref_im[c * PD + p];
    const __half* bu = g_Buh + (size_t)c * CHUNK * N1 + 2 * p;
    __half*       xs = g_xsh + (size_t)c * CHUNK * N1 + 2 * p;
    #pragma unroll 8
    for (int i = 0; i < CHUNK; i++) {
        float2 b = __half22float2(*(const __half2*)(bu + i * N1));
        float br = b.x * BSCALE_INV, bi = b.y * BSCALE_INV;
        float nr = fmaf(Ar, hr, fmaf(-Ai, hi, br));
        float ni = fmaf(Ar, hi, fmaf(Ai, hr, bi));
        hr = nr; hi = ni;
        *(uint32_t*)(xs + i * N1) = pack_h2(hr, hi);
    }
}

// ---------------- LayerNorm (in place, float4) ----------------
__global__ __launch_bounds__(256) void ln_kernel(float* __restrict__ out,
                                                 const float* __restrict__ gamma,
                                                 const float* __restrict__ beta)
{
    __shared__ float sh_s[8], sh_s2[8], sh_mr[2];
    int row = blockIdx.x;
    float* r = out + (size_t)row * HD;
    int tid = threadIdx.x;
    float4 v = *(const float4*)(r + tid * 4);
    float s  = v.x + v.y + v.z + v.w;
    float s2 = fmaf(v.x, v.x, fmaf(v.y, v.y, fmaf(v.z, v.z, v.w * v.w)));
    #pragma unroll
    for (int o = 16; o > 0; o >>= 1) {
        s  += __shfl_down_sync(0xffffffffu, s,  o);
        s2 += __shfl_down_sync(0xffffffffu, s2, o);
    }
    if ((tid & 31) == 0) { sh_s[tid >> 5] = s; sh_s2[tid >> 5] = s2; }
    __syncthreads();
    if (tid == 0) {
        float ts = 0.f, ts2 = 0.f;
        #pragma unroll
        for (int w = 0; w < 8; w++) { ts += sh_s[w]; ts2 += sh_s2[w]; }
        float mean = ts * (1.f / HD);
        float var  = ts2 * (1.f / HD) - mean * mean;
        sh_mr[0] = mean;
        sh_mr[1] = rsqrtf(var + 1e-5f);
    }
    __syncthreads();
    float mean = sh_mr[0], rstd = sh_mr[1];
    float4 gv = *(const float4*)(gamma + tid * 4);
    float4 bv = *(const float4*)(beta + tid * 4);
    float4 o;
    o.x = (v.x - mean) * rstd * gv.x + bv.x;
    o.y = (v.y - mean) * rstd * gv.y + bv.y;
    o.z = (v.z - mean) * rstd * gv.z + bv.z;
    o.w = (v.w - mean) * rstd * gv.w + bv.w;
    *(float4*)(r + tid * 4) = o;
}

// ---------------- launch ----------------
extern "C" void kernel_launch(void* const* d_in, const int* in_sizes, int n_in,
                              void* d_out, int out_size)
{
    const float* x     = (const float*)d_in[0];
    const float* Lre   = (const float*)d_in[1];
    const float* Lim   = (const float*)d_in[2];
    const float* Bre   = (const float*)d_in[3];
    const float* Bim   = (const float*)d_in[4];
    const float* Cre   = (const float*)d_in[5];
    const float* Cim   = (const float*)d_in[6];
    const float* D     = (const float*)d_in[7];
    const float* logdt = (const float*)d_in[8];
    const float* gamma = (const float*)d_in[9];
    const float* beta  = (const float*)d_in[10];
    float* out = (float*)d_out;

    cudaFuncSetAttribute(gemm_mma<HD, true>,  cudaFuncAttributeMaxDynamicSharedMemorySize, SMEM_BYTES);
    cudaFuncSetAttribute(gemm_mma<N1, false>, cudaFuncAttributeMaxDynamicSharedMemorySize, SMEM_BYTES);

    setup_kernel<<<4, 256>>>(Lre, Lim, logdt);
    conv_x<<<LQ * HD / 8 / 256, 256>>>(x);
    build_bbar<<<PD * HD / 4 / 256, 256>>>(Bre, Bim);
    build_cfused<<<HD * PD / 4 / 256, 256>>>(Cre, Cim);

    // Bu = x @ Bbar^T   (M=8192, N=2048, K=1024), output fp16
    gemm_mma<HD, true><<<dim3(N1 / BN, LQ / BM), 256, SMEM_BYTES>>>(nullptr, nullptr, nullptr);

    scan_phase1<<<dim3(NCHUNK, PD / 256), 256>>>();
    scan_phase2<<<PD / 128, 128>>>();
    scan_phase3<<<dim3(NCHUNK, PD / 256), 256>>>();

    // out = 2*Re(xs @ C^T) + x*(1+D)   (M=8192, N=1024, K=2048)
    gemm_mma<N1, false><<<dim3(HD / BN, LQ / BM), 256, SMEM_BYTES>>>(out, x, D);

    ln_kernel<<<LQ, 256>>>(out, gamma, beta);
}